// round 17
// baseline (speedup 1.0000x reference)
#include <cuda_runtime.h>
#include <math.h>

// Scratch (allocation-free rule: __device__ globals)
__device__ float g_dct[128 * 3 * 64];   // dct branch input, (b,c,8,8)
__device__ float g_grad[128 * 3 * 64];  // grad branch input, (b,c,8,8)

// ---------------------------------------------------------------------------
// Kernel 1: R16 form (MLP-8 batched pass 1 + inline A). grid=384, block=256.
// ---------------------------------------------------------------------------
__global__ void __launch_bounds__(256) dct_grad_kernel(const float* __restrict__ x) {
    __shared__ float Rf2[8][25];
    __shared__ float As[256][8];       // As[m][o] = A[o][m]   (8 KB)
    __shared__ float Tp[4][8][256];    // team partials, later aliased as Ts (32 KB)

    const int tid = threadIdx.x;
    const int blk = blockIdx.x;
    const float* __restrict__ xc = x + (size_t)blk * 65536;

    if (tid < 200) {
        const int o = tid / 25, k = tid % 25;
        float sk = (k == 0) ? sqrtf(1.0f / 256.0f) : sqrtf(2.0f / 256.0f);
        float si = sqrtf(2.0f / 256.0f);
        float tw = (float)(2 * k + 1) * (1.0f / 512.0f);   // exact
        float c0 = cospif(tw * (float)(32 * o + 15));
        float c1 = cospif(tw * (float)(32 * o + 16));
        Rf2[o][k] = 0.5f * si * sk * (c0 + c1);
    }
    __syncthreads();
    {
        const float th = (float)(2 * tid + 1) * (1.0f / 512.0f);  // exact
        float cp = cospif(th);
        const float twoc = 2.0f * cp;
        float cpp = 1.0f;
        float a[8];
#pragma unroll
        for (int o = 0; o < 8; o++) a[o] = fmaf(Rf2[o][1], cp, Rf2[o][0]);
#pragma unroll
        for (int k = 2; k < 25; k++) {
            float ck = fmaf(twoc, cp, -cpp);
#pragma unroll
            for (int o = 0; o < 8; o++) a[o] = fmaf(Rf2[o][k], ck, a[o]);
            cpp = cp; cp = ck;
        }
#pragma unroll
        for (int o = 0; o < 8; o++) As[tid][o] = a[o];
    }
    __syncthreads();

    const int team = tid >> 6;         // rows 64*team .. 64*team+63
    const int t64  = tid & 63;         // columns 4*t64 .. 4*t64+3

    float acc[8][4];
#pragma unroll
    for (int o = 0; o < 8; o++)
#pragma unroll
        for (int c = 0; c < 4; c++) acc[o][c] = 0.0f;

    const float4* __restrict__ xrow = reinterpret_cast<const float4*>(xc) + t64;
    const int mbase = team * 64;

#pragma unroll
    for (int chunk = 0; chunk < 8; chunk++) {
        float4 xv[8];
#pragma unroll
        for (int u = 0; u < 8; u++)
            xv[u] = xrow[(size_t)(mbase + chunk * 8 + u) * 64];
#pragma unroll
        for (int u = 0; u < 8; u++) {
            const int m = mbase + chunk * 8 + u;
            float4 a0 = *reinterpret_cast<const float4*>(&As[m][0]);
            float4 a1 = *reinterpret_cast<const float4*>(&As[m][4]);
            acc[0][0] = fmaf(a0.x, xv[u].x, acc[0][0]);
            acc[0][1] = fmaf(a0.x, xv[u].y, acc[0][1]);
            acc[0][2] = fmaf(a0.x, xv[u].z, acc[0][2]);
            acc[0][3] = fmaf(a0.x, xv[u].w, acc[0][3]);
            acc[1][0] = fmaf(a0.y, xv[u].x, acc[1][0]);
            acc[1][1] = fmaf(a0.y, xv[u].y, acc[1][1]);
            acc[1][2] = fmaf(a0.y, xv[u].z, acc[1][2]);
            acc[1][3] = fmaf(a0.y, xv[u].w, acc[1][3]);
            acc[2][0] = fmaf(a0.z, xv[u].x, acc[2][0]);
            acc[2][1] = fmaf(a0.z, xv[u].y, acc[2][1]);
            acc[2][2] = fmaf(a0.z, xv[u].z, acc[2][2]);
            acc[2][3] = fmaf(a0.z, xv[u].w, acc[2][3]);
            acc[3][0] = fmaf(a0.w, xv[u].x, acc[3][0]);
            acc[3][1] = fmaf(a0.w, xv[u].y, acc[3][1]);
            acc[3][2] = fmaf(a0.w, xv[u].z, acc[3][2]);
            acc[3][3] = fmaf(a0.w, xv[u].w, acc[3][3]);
            acc[4][0] = fmaf(a1.x, xv[u].x, acc[4][0]);
            acc[4][1] = fmaf(a1.x, xv[u].y, acc[4][1]);
            acc[4][2] = fmaf(a1.x, xv[u].z, acc[4][2]);
            acc[4][3] = fmaf(a1.x, xv[u].w, acc[4][3]);
            acc[5][0] = fmaf(a1.y, xv[u].x, acc[5][0]);
            acc[5][1] = fmaf(a1.y, xv[u].y, acc[5][1]);
            acc[5][2] = fmaf(a1.y, xv[u].z, acc[5][2]);
            acc[5][3] = fmaf(a1.y, xv[u].w, acc[5][3]);
            acc[6][0] = fmaf(a1.z, xv[u].x, acc[6][0]);
            acc[6][1] = fmaf(a1.z, xv[u].y, acc[6][1]);
            acc[6][2] = fmaf(a1.z, xv[u].z, acc[6][2]);
            acc[6][3] = fmaf(a1.z, xv[u].w, acc[6][3]);
            acc[7][0] = fmaf(a1.w, xv[u].x, acc[7][0]);
            acc[7][1] = fmaf(a1.w, xv[u].y, acc[7][1]);
            acc[7][2] = fmaf(a1.w, xv[u].z, acc[7][2]);
            acc[7][3] = fmaf(a1.w, xv[u].w, acc[7][3]);
        }
    }
#pragma unroll
    for (int o = 0; o < 8; o++)
        *reinterpret_cast<float4*>(&Tp[team][o][t64 * 4]) =
            make_float4(acc[o][0], acc[o][1], acc[o][2], acc[o][3]);
    __syncthreads();

    float* TsF = &Tp[0][0][0];   // Ts[o][c] = TsF[o*256 + c]
    {
        float s[8];
#pragma unroll
        for (int o = 0; o < 8; o++)
            s[o] = Tp[0][o][tid] + Tp[1][o][tid] + Tp[2][o][tid] + Tp[3][o][tid];
#pragma unroll
        for (int o = 0; o < 8; o++) TsF[o * 256 + tid] = s[o];
    }
    __syncthreads();

    if (tid < 64) {
        const int oy = tid >> 3, ox = tid & 7;
        const float* tsr = TsF + oy * 256;
        float s = 0.0f;
#pragma unroll 8
        for (int j = 0; j < 256; j++)
            s = fmaf(tsr[j], As[j][ox], s);
        g_dct[blk * 64 + tid] = s;
    } else if (tid < 128) {
        const int cl = tid - 64;
        const int r = 32 * (cl >> 3) + 15;
        const int c = 32 * (cl & 7) + 15;
        float p[4][4];
#pragma unroll
        for (int a = 0; a < 4; a++)
#pragma unroll
            for (int b = 0; b < 4; b++)
                p[a][b] = xc[(r - 1 + a) * 256 + (c - 1 + b)];
        float gsum = 0.0f;
#pragma unroll
        for (int i = 0; i < 2; i++)
#pragma unroll
            for (int j = 0; j < 2; j++) {
                float gx = (p[i][j + 2] - p[i][j])
                         + 2.0f * (p[i + 1][j + 2] - p[i + 1][j])
                         + (p[i + 2][j + 2] - p[i + 2][j]);
                float gy = (p[i + 2][j] - p[i][j])
                         + 2.0f * (p[i + 2][j + 1] - p[i][j + 1])
                         + (p[i + 2][j + 2] - p[i][j + 2]);
                gsum += sqrtf(gx * gx + gy * gy);
            }
        g_grad[blk * 64 + cl] = 0.25f * gsum;
    }
}

// ---------------------------------------------------------------------------
// Kernel 2: head, block = 1024 (thread = (br, co, oy), one branch per thread).
// grid = 128. Warps 0-15 = dct branch, 16-31 = grad branch.
// ---------------------------------------------------------------------------
__global__ void __launch_bounds__(1024) head_kernel(
    const float* __restrict__ cw_d, const float* __restrict__ cb_d,
    const float* __restrict__ bg_d, const float* __restrict__ bb_d,
    const float* __restrict__ cw_g, const float* __restrict__ cb_g,
    const float* __restrict__ bg_g, const float* __restrict__ bb_g,
    const float* __restrict__ fw, const float* __restrict__ fb,
    const float* __restrict__ clsw, const float* __restrict__ clsb,
    float* __restrict__ out)
{
    __shared__ float tile[2][3][10][10];
    __shared__ float wsm[2][64][28];
    __shared__ float red[1024];
    __shared__ float warpred[32][2];   // per warp: C0, C1
    __shared__ float sfw[64];

    const int b = blockIdx.x;
    const int tid = threadIdx.x;

    for (int t = tid; t < 64 * 27; t += 1024) {
        int co_ = t / 27, i_ = t % 27;
        wsm[0][co_][i_] = cw_d[t];
        wsm[1][co_][i_] = cw_g[t];
    }
    for (int t = tid; t < 600; t += 1024) {
        int br_ = t / 300, rem_ = t % 300;
        int c = rem_ / 100, yy = (rem_ % 100) / 10, xx = rem_ % 10;
        float v = 0.0f;
        if (yy >= 1 && yy <= 8 && xx >= 1 && xx <= 8) {
            const float* src = br_ ? g_grad : g_dct;
            v = src[(b * 3 + c) * 64 + (yy - 1) * 8 + (xx - 1)];
        }
        tile[br_][c][yy][xx] = v;
    }
    __syncthreads();

    const int br  = tid >> 9;          // 0 = dct, 1 = grad
    const int rem = tid & 511;
    const int co  = rem >> 3;          // 0..63
    const int oy  = rem & 7;           // 0..7

    const float rs = rsqrtf(1.0f + 1e-5f);
    const float kbn = (br ? bg_g[co] : bg_d[co]) * rs;
    const float bbn = (br ? cb_g[co] : cb_d[co]) * kbn + (br ? bb_g[co] : bb_d[co]);

    float v[8];
    {
        const float* wr = &wsm[br][co][0];
#pragma unroll
        for (int i = 0; i < 8; i++) {
            float a = 0.0f;
#pragma unroll
            for (int ci = 0; ci < 3; ci++)
#pragma unroll
                for (int ky = 0; ky < 3; ky++)
#pragma unroll
                    for (int kx = 0; kx < 3; kx++)
                        a = fmaf(tile[br][ci][oy + ky][i + kx], wr[ci * 9 + ky * 3 + kx], a);
            v[i] = fmaxf(fmaf(a, kbn, bbn), 0.0f);
        }
    }

    // gate partial (per (br,co,oy))
    float psum = 0.0f;
#pragma unroll
    for (int i = 0; i < 8; i++) psum += v[i];
    red[tid] = psum;

    // classifier partials: flat = co*64 + oy*8 + i = rem*8 + i (float4 loads)
    float a0, a1;
    {
        const float4* __restrict__ c0 = reinterpret_cast<const float4*>(clsw) + rem * 2;
        const float4* __restrict__ c1 = reinterpret_cast<const float4*>(clsw + 4096) + rem * 2;
        float4 w00 = c0[0], w01 = c0[1];
        float4 w10 = c1[0], w11 = c1[1];
        a0 = v[0]*w00.x + v[1]*w00.y + v[2]*w00.z + v[3]*w00.w
           + v[4]*w01.x + v[5]*w01.y + v[6]*w01.z + v[7]*w01.w;
        a1 = v[0]*w10.x + v[1]*w10.y + v[2]*w10.z + v[3]*w10.w
           + v[4]*w11.x + v[5]*w11.y + v[6]*w11.z + v[7]*w11.w;
    }
#pragma unroll
    for (int off = 16; off > 0; off >>= 1) {
        a0 += __shfl_down_sync(0xffffffffu, a0, off);
        a1 += __shfl_down_sync(0xffffffffu, a1, off);
    }
    if ((tid & 31) == 0) {
        warpred[tid >> 5][0] = a0;
        warpred[tid >> 5][1] = a1;
    }
    __syncthreads();

    if (tid < 64) {
        float s = 0.0f;
#pragma unroll
        for (int k = 0; k < 8; k++)
            s += red[tid * 8 + k] + red[512 + tid * 8 + k];
        sfw[tid] = (s * (1.0f / 64.0f)) * fw[tid];
    }
    __syncthreads();

    if (tid == 0) {
        float tot = fb[0];
#pragma unroll
        for (int c2 = 0; c2 < 64; c2++) tot += sfw[c2];
        float w = 1.0f / (1.0f + expf(-tot));
        float D0 = 0.f, D1 = 0.f, G0 = 0.f, G1 = 0.f;
#pragma unroll
        for (int wd = 0; wd < 16; wd++) {
            D0 += warpred[wd][0];
            D1 += warpred[wd][1];
            G0 += warpred[16 + wd][0];
            G1 += warpred[16 + wd][1];
        }
        out[b * 2 + 0] = w * D0 + (1.0f - w) * G0 + clsb[0];
        out[b * 2 + 1] = w * D1 + (1.0f - w) * G1 + clsb[1];
    }
}

// ---------------------------------------------------------------------------
extern "C" void kernel_launch(void* const* d_in, const int* in_sizes, int n_in,
                              void* d_out, int out_size) {
    const float* x     = (const float*)d_in[0];
    const float* cw_d  = (const float*)d_in[1];
    const float* cb_d  = (const float*)d_in[2];
    const float* bg_d  = (const float*)d_in[3];
    const float* bb_d  = (const float*)d_in[4];
    const float* cw_g  = (const float*)d_in[5];
    const float* cb_g  = (const float*)d_in[6];
    const float* bg_g  = (const float*)d_in[7];
    const float* bb_g  = (const float*)d_in[8];
    const float* fw    = (const float*)d_in[9];
    const float* fb    = (const float*)d_in[10];
    const float* clsw  = (const float*)d_in[11];
    const float* clsb  = (const float*)d_in[12];
    float* out = (float*)d_out;

    dct_grad_kernel<<<384, 256>>>(x);
    head_kernel<<<128, 1024>>>(cw_d, cb_d, bg_d, bb_d,
                               cw_g, cb_g, bg_g, bb_g,
                               fw, fb, clsw, clsb, out);
}